// round 5
// baseline (speedup 1.0000x reference)
#include <cuda_runtime.h>
#include <math.h>

// Spiking CNN forward, B=4096:
//  conv1(1->10,3x3,SAME)->spike(>=1)->pool2 -> conv2(10->20)->spike->pool2 -> z[980]
//  h = z @ Wf1^T ; 32-step LIF(v1)->o1 ; y=o1@Wf2^T ; LIF(v2)->cnt ; softmax(cnt/32)

#define NB 4096
typedef unsigned long long u64;
typedef unsigned int uint32;

__device__ float g_Zt[980 * NB];        // conv output, TRANSPOSED: [k][m]
__device__ float g_Wt2[980 * 256];      // Wf1 transposed+padded, weights duplicated:
                                        // g_Wt2[k][2n]=g_Wt2[k][2n+1]=Wf1[n][k], n<128 pad 0

// ---- packed f32x2 helpers ----
__device__ __forceinline__ u64 splat2(float a){
    u64 r; asm("mov.b64 %0, {%1, %1};" : "=l"(r) : "f"(a)); return r;
}
__device__ __forceinline__ u64 pack2(float a, float b){
    u64 r; asm("mov.b64 %0, {%1, %2};" : "=l"(r) : "f"(a), "f"(b)); return r;
}
__device__ __forceinline__ void unpack2(u64 v, float &x, float &y){
    asm("mov.b64 {%0, %1}, %2;" : "=f"(x), "=f"(y) : "l"(v));
}
__device__ __forceinline__ u64 fma2(u64 a, u64 b, u64 c){
    u64 d; asm("fma.rn.f32x2 %0, %1, %2, %3;" : "=l"(d) : "l"(a), "l"(b), "l"(c));
    return d;
}

// ===========================================================================
// kT: build g_Wt2 from Wf1 [100][980]
// ===========================================================================
__global__ void __launch_bounds__(256)
kT(const float* __restrict__ Wf1)
{
    int idx = blockIdx.x * 256 + threadIdx.x;      // over 980*128
    if (idx < 980 * 128) {
        int k = idx >> 7, n = idx & 127;
        float w = (n < 100) ? Wf1[n * 980 + k] : 0.f;
        g_Wt2[k * 256 + 2 * n]     = w;
        g_Wt2[k * 256 + 2 * n + 1] = w;
    }
}

// ===========================================================================
// K1: fused conv stack, 2 samples per block, 160 threads, f32x2 over oc-pairs
// ===========================================================================
#define K1_SMEM 58280

__global__ void __launch_bounds__(160)
k1_conv(const float* __restrict__ x, const float* __restrict__ Wc1,
        const float* __restrict__ Wc2)
{
    extern __shared__ char smraw[];
    float* xs  = (float*)(smraw);            // [2][30][30]
    u64*   w1p = (u64*)  (smraw + 7200);     // [5 ocp][9]
    u64*   w2p = (u64*)  (smraw + 7560);     // [10 ocp][90]
    float* p1s = (float*)(smraw + 14760);    // [2][10][16][34] (each val twice)

    const int tid = threadIdx.x;
    const int s0  = blockIdx.x * 2;

    for (int i = tid; i < 1800; i += 160) {
        int sp = i / 900, e = i - sp * 900;
        int r = e / 30, c = e - r * 30;
        float v = 0.f;
        if (r >= 1 && r <= 28 && c >= 1 && c <= 28)
            v = x[(s0 + sp) * 784 + (r - 1) * 28 + (c - 1)];
        xs[i] = v;
    }
    if (tid < 45) {
        int cp = tid / 9, k = tid - cp * 9;
        w1p[tid] = pack2(Wc1[(2 * cp) * 9 + k], Wc1[(2 * cp + 1) * 9 + k]);
    }
    for (int i = tid; i < 900; i += 160) {
        int ocp = i / 90, t = i - ocp * 90;
        w2p[i] = pack2(Wc2[(2 * ocp) * 90 + t], Wc2[(2 * ocp + 1) * 90 + t]);
    }
    for (int i = tid; i < 10880; i += 160) p1s[i] = 0.f;
    __syncthreads();

    // conv1 + spike + pool
    for (int task = tid; task < 1960; task += 160) {
        int sp  = task / 980;
        int r   = task - sp * 980;
        int cp  = r / 196;
        int pos = r - cp * 196;
        int py = pos / 14, px = pos - py * 14;
        const float* xb = xs + sp * 900 + (2 * py) * 30 + 2 * px;
        u64 acc[2][2];
        acc[0][0] = acc[0][1] = acc[1][0] = acc[1][1] = 0ull;
        #pragma unroll
        for (int rr = 0; rr < 4; rr++) {
            u64 cc[4];
            #pragma unroll
            for (int c = 0; c < 4; c++) cc[c] = splat2(xb[rr * 30 + c]);
            #pragma unroll
            for (int dy = 0; dy < 2; dy++) {
                int ky = rr - dy;
                if (ky >= 0 && ky <= 2) {
                    #pragma unroll
                    for (int kx = 0; kx < 3; kx++) {
                        u64 w = w1p[cp * 9 + ky * 3 + kx];
                        acc[dy][0] = fma2(cc[kx],     w, acc[dy][0]);
                        acc[dy][1] = fma2(cc[kx + 1], w, acc[dy][1]);
                    }
                }
            }
        }
        float f0 = 0.f, f1 = 0.f, lo, hi;
        #pragma unroll
        for (int dy = 0; dy < 2; dy++)
            #pragma unroll
            for (int dx = 0; dx < 2; dx++) {
                unpack2(acc[dy][dx], lo, hi);
                if (lo >= 1.f) f0 = 1.f;
                if (hi >= 1.f) f1 = 1.f;
            }
        int base = ((sp * 10 + 2 * cp) * 16 + (py + 1)) * 34 + 2 * (px + 1);
        p1s[base]       = f0; p1s[base + 1]   = f0;
        p1s[base + 544] = f1; p1s[base + 545] = f1;
    }
    __syncthreads();

    // conv2 + spike + pool  -> transposed store to g_Zt
    if (tid < 140) {
        int sp  = tid / 70;
        int r70 = tid - sp * 70;
        int ocp = r70 / 7, py = r70 - ocp * 7;
        u64 acc[2][14];
        #pragma unroll
        for (int i = 0; i < 2; i++)
            #pragma unroll
            for (int j = 0; j < 14; j++) acc[i][j] = 0ull;

        const float* pbase = p1s + sp * 5440 + (2 * py) * 34;
        const u64*   wq    = w2p + ocp * 90;

        for (int ic = 0; ic < 10; ic++) {
            u64 w[9];
            #pragma unroll
            for (int k = 0; k < 9; k++) w[k] = wq[ic * 9 + k];
            const float* prow = pbase + ic * 544;
            #pragma unroll
            for (int rr = 0; rr < 4; rr++) {
                u64 arow[16];
                #pragma unroll
                for (int c = 0; c < 16; c++)
                    arow[c] = *(const u64*)(prow + rr * 34 + 2 * c);
                #pragma unroll
                for (int pr = 0; pr < 2; pr++) {
                    int ky = rr - pr;
                    if (ky >= 0 && ky <= 2) {
                        #pragma unroll
                        for (int kx = 0; kx < 3; kx++) {
                            u64 wv = w[ky * 3 + kx];
                            #pragma unroll
                            for (int ox = 0; ox < 14; ox++)
                                acc[pr][ox] = fma2(arow[ox + kx], wv, acc[pr][ox]);
                        }
                    }
                }
            }
        }
        int s = s0 + sp;
        int z0 = (2 * ocp) * 49 + py * 7;
        #pragma unroll
        for (int px = 0; px < 7; px++) {
            float a, b, c, d, e, f, g, h;
            unpack2(acc[0][2 * px],     a, b);
            unpack2(acc[0][2 * px + 1], c, d);
            unpack2(acc[1][2 * px],     e, f);
            unpack2(acc[1][2 * px + 1], g, h);
            g_Zt[(z0 + px) * NB + s]      = (a >= 1.f || c >= 1.f || e >= 1.f || g >= 1.f) ? 1.f : 0.f;
            g_Zt[(z0 + 49 + px) * NB + s] = (b >= 1.f || d >= 1.f || f >= 1.f || h >= 1.f) ? 1.f : 0.f;
        }
    }
}

// ===========================================================================
// K2K3: 16 samples / block, 256 threads, grid 256.
// ===========================================================================
__device__ __forceinline__ uint32 lifmask(float h){
    float v = 0.f; uint32 m = 0u;
    #pragma unroll
    for (int t = 0; t < 32; t++) {
        v += (h - v) * 0.5f;
        if (v >= 1.f) { m |= (1u << t); v = 0.f; }
    }
    return m;
}

__global__ void __launch_bounds__(256)
k2k3(const float* __restrict__ Wf2, float* __restrict__ out)
{
    __shared__ uint32 Msk[16 * 101];
    __shared__ float  W2s[1000];
    __shared__ float  ysm[16 * 321];
    __shared__ float  cs[16 * 12];

    const int tid = threadIdx.x;
    const int tx  = tid & 31, ty = tid >> 5;     // warp ty: samples 2ty, 2ty+1
    const int m0  = blockIdx.x * 16;

    for (int e = tid; e < 1000; e += 256) W2s[e] = Wf2[e];

    // ---- Phase A: h = z @ Wf1^T  (lanes = sample pair; regs = 4 n-cols) ----
    u64 a0 = 0, a1 = 0, a2 = 0, a3 = 0;
    {
        const float* zp = g_Zt + (m0 + 2 * ty);
        const ulonglong2* wp = (const ulonglong2*)(g_Wt2 + (tx << 3));
        #pragma unroll 4
        for (int k = 0; k < 980; k++) {
            u64 z = *(const u64*)(zp + k * NB);
            ulonglong2 q0 = wp[k * 64];          // row stride: 256 floats = 64 ulonglong2
            ulonglong2 q1 = wp[k * 64 + 1];
            a0 = fma2(z, q0.x, a0);
            a1 = fma2(z, q0.y, a1);
            a2 = fma2(z, q1.x, a2);
            a3 = fma2(z, q1.y, a3);
        }
    }

    // ---- Phase B: LIF-1 masks ----
    if (tx < 25) {
        int n = 4 * tx;
        int mA = 2 * ty, mB = 2 * ty + 1;
        float h0, h1;
        unpack2(a0, h0, h1);
        Msk[mA * 101 + n]     = lifmask(h0); Msk[mB * 101 + n]     = lifmask(h1);
        unpack2(a1, h0, h1);
        Msk[mA * 101 + n + 1] = lifmask(h0); Msk[mB * 101 + n + 1] = lifmask(h1);
        unpack2(a2, h0, h1);
        Msk[mA * 101 + n + 2] = lifmask(h0); Msk[mB * 101 + n + 2] = lifmask(h1);
        unpack2(a3, h0, h1);
        Msk[mA * 101 + n + 3] = lifmask(h0); Msk[mB * 101 + n + 3] = lifmask(h1);
    }
    __syncthreads();

    // ---- Phase C: thread (m = tid>>4, tq = tid&15) handles t = tq, tq+16 ----
    {
        int m = tid >> 4, tq = tid & 15;
        float y0[10], y1[10];
        #pragma unroll
        for (int i = 0; i < 10; i++) { y0[i] = 0.f; y1[i] = 0.f; }
        for (int j = 0; j < 100; j++) {
            uint32 mk = Msk[m * 101 + j];
            float b0 = (float)((mk >> tq) & 1u);
            float b1 = (float)((mk >> (tq + 16)) & 1u);
            #pragma unroll
            for (int i = 0; i < 10; i++) {
                float w = W2s[i * 100 + j];
                y0[i] = fmaf(b0, w, y0[i]);
                y1[i] = fmaf(b1, w, y1[i]);
            }
        }
        #pragma unroll
        for (int i = 0; i < 10; i++) {
            ysm[m * 321 + tq * 10 + i]        = y0[i];
            ysm[m * 321 + (tq + 16) * 10 + i] = y1[i];
        }
    }
    __syncthreads();

    // ---- Phase D: (m, i) per thread ----
    if (tid < 160) {
        int m = tid / 10, i = tid - m * 10;
        float v = 0.f, cnt = 0.f;
        #pragma unroll
        for (int t = 0; t < 32; t++) {
            float yv = ysm[m * 321 + t * 10 + i];
            v += (yv - v) * 0.5f;
            if (v >= 1.f) { cnt += 1.f; v = 0.f; }
        }
        cs[m * 12 + i] = cnt * (1.f / 32.f);
    }
    __syncthreads();
    if (tid < 160) {
        int m = tid / 10, i = tid - m * 10;
        float mx = -1e30f;
        #pragma unroll
        for (int q = 0; q < 10; q++) mx = fmaxf(mx, cs[m * 12 + q]);
        float sum = 0.f;
        #pragma unroll
        for (int q = 0; q < 10; q++) sum += expf(cs[m * 12 + q] - mx);
        out[(m0 + m) * 10 + i] = expf(cs[m * 12 + i] - mx) / sum;
    }
}

// ===========================================================================
extern "C" void kernel_launch(void* const* d_in, const int* in_sizes, int n_in,
                              void* d_out, int out_size)
{
    const float* x   = (const float*)d_in[0];
    const float* Wc1 = (const float*)d_in[1];
    const float* Wc2 = (const float*)d_in[2];
    const float* Wf1 = (const float*)d_in[3];
    const float* Wf2 = (const float*)d_in[4];
    float* out = (float*)d_out;

    cudaFuncSetAttribute(k1_conv, cudaFuncAttributeMaxDynamicSharedMemorySize, K1_SMEM);

    kT<<<(980 * 128 + 255) / 256, 256>>>(Wf1);
    k1_conv<<<NB / 2, 160, K1_SMEM>>>(x, Wc1, Wc2);
    k2k3<<<NB / 16, 256>>>(Wf2, out);
}

// round 7
// speedup vs baseline: 1.5057x; 1.5057x over previous
#include <cuda_runtime.h>
#include <math.h>

// Spiking CNN forward, B=4096.

#define NB 4096
typedef unsigned long long u64;
typedef unsigned int uint32;

__device__ float g_Z[NB * 980];          // binary conv-stack output [m][k]
__device__ float g_Wt[980 * 112];        // Wf1 transposed+padded: g_Wt[k][n]=Wf1[n][k]
__device__ float g_P[4 * NB * 112];      // split-K partial H

// ---- packed f32x2 helpers ----
__device__ __forceinline__ u64 splat2(float a){
    u64 r; asm("mov.b64 %0, {%1, %1};" : "=l"(r) : "f"(a)); return r;
}
__device__ __forceinline__ u64 pack2(float a, float b){
    u64 r; asm("mov.b64 %0, {%1, %2};" : "=l"(r) : "f"(a), "f"(b)); return r;
}
__device__ __forceinline__ void unpack2(u64 v, float &x, float &y){
    asm("mov.b64 {%0, %1}, %2;" : "=f"(x), "=f"(y) : "l"(v));
}
__device__ __forceinline__ u64 fma2(u64 a, u64 b, u64 c){
    u64 d; asm("fma.rn.f32x2 %0, %1, %2, %3;" : "=l"(d) : "l"(a), "l"(b), "l"(c));
    return d;
}

// ===========================================================================
// kT: g_Wt[k][n] = Wf1[n][k]  (pad n>=100 with 0)
// ===========================================================================
__global__ void __launch_bounds__(256)
kT(const float* __restrict__ Wf1)
{
    int idx = blockIdx.x * 256 + threadIdx.x;
    if (idx < 980 * 112) {
        int k = idx / 112, n = idx - k * 112;
        g_Wt[idx] = (n < 100) ? Wf1[n * 980 + k] : 0.f;
    }
}

// ===========================================================================
// K1: fused conv stack (R3 version; g_Z row-major)
// ===========================================================================
#define K1_SMEM 58280

__global__ void __launch_bounds__(160)
k1_conv(const float* __restrict__ x, const float* __restrict__ Wc1,
        const float* __restrict__ Wc2)
{
    extern __shared__ char smraw[];
    float* xs  = (float*)(smraw);            // [2][30][30]
    u64*   w1p = (u64*)  (smraw + 7200);     // [5 ocp][9]
    u64*   w2p = (u64*)  (smraw + 7560);     // [10 ocp][90]
    float* p1s = (float*)(smraw + 14760);    // [2][10][16][34]

    const int tid = threadIdx.x;
    const int s0  = blockIdx.x * 2;

    for (int i = tid; i < 1800; i += 160) {
        int sp = i / 900, e = i - sp * 900;
        int r = e / 30, c = e - r * 30;
        float v = 0.f;
        if (r >= 1 && r <= 28 && c >= 1 && c <= 28)
            v = x[(s0 + sp) * 784 + (r - 1) * 28 + (c - 1)];
        xs[i] = v;
    }
    if (tid < 45) {
        int cp = tid / 9, k = tid - cp * 9;
        w1p[tid] = pack2(Wc1[(2 * cp) * 9 + k], Wc1[(2 * cp + 1) * 9 + k]);
    }
    for (int i = tid; i < 900; i += 160) {
        int ocp = i / 90, t = i - ocp * 90;
        w2p[i] = pack2(Wc2[(2 * ocp) * 90 + t], Wc2[(2 * ocp + 1) * 90 + t]);
    }
    for (int i = tid; i < 10880; i += 160) p1s[i] = 0.f;
    __syncthreads();

    for (int task = tid; task < 1960; task += 160) {
        int sp  = task / 980;
        int r   = task - sp * 980;
        int cp  = r / 196;
        int pos = r - cp * 196;
        int py = pos / 14, px = pos - py * 14;
        const float* xb = xs + sp * 900 + (2 * py) * 30 + 2 * px;
        u64 acc[2][2];
        acc[0][0] = acc[0][1] = acc[1][0] = acc[1][1] = 0ull;
        #pragma unroll
        for (int rr = 0; rr < 4; rr++) {
            u64 cc[4];
            #pragma unroll
            for (int c = 0; c < 4; c++) cc[c] = splat2(xb[rr * 30 + c]);
            #pragma unroll
            for (int dy = 0; dy < 2; dy++) {
                int ky = rr - dy;
                if (ky >= 0 && ky <= 2) {
                    #pragma unroll
                    for (int kx = 0; kx < 3; kx++) {
                        u64 w = w1p[cp * 9 + ky * 3 + kx];
                        acc[dy][0] = fma2(cc[kx],     w, acc[dy][0]);
                        acc[dy][1] = fma2(cc[kx + 1], w, acc[dy][1]);
                    }
                }
            }
        }
        float f0 = 0.f, f1 = 0.f, lo, hi;
        #pragma unroll
        for (int dy = 0; dy < 2; dy++)
            #pragma unroll
            for (int dx = 0; dx < 2; dx++) {
                unpack2(acc[dy][dx], lo, hi);
                if (lo >= 1.f) f0 = 1.f;
                if (hi >= 1.f) f1 = 1.f;
            }
        int base = ((sp * 10 + 2 * cp) * 16 + (py + 1)) * 34 + 2 * (px + 1);
        p1s[base]       = f0; p1s[base + 1]   = f0;
        p1s[base + 544] = f1; p1s[base + 545] = f1;
    }
    __syncthreads();

    if (tid < 140) {
        int sp  = tid / 70;
        int r70 = tid - sp * 70;
        int ocp = r70 / 7, py = r70 - ocp * 7;
        u64 acc[2][14];
        #pragma unroll
        for (int i = 0; i < 2; i++)
            #pragma unroll
            for (int j = 0; j < 14; j++) acc[i][j] = 0ull;

        const float* pbase = p1s + sp * 5440 + (2 * py) * 34;
        const u64*   wq    = w2p + ocp * 90;

        for (int ic = 0; ic < 10; ic++) {
            u64 w[9];
            #pragma unroll
            for (int k = 0; k < 9; k++) w[k] = wq[ic * 9 + k];
            const float* prow = pbase + ic * 544;
            #pragma unroll
            for (int rr = 0; rr < 4; rr++) {
                u64 arow[16];
                #pragma unroll
                for (int c = 0; c < 16; c++)
                    arow[c] = *(const u64*)(prow + rr * 34 + 2 * c);
                #pragma unroll
                for (int pr = 0; pr < 2; pr++) {
                    int ky = rr - pr;
                    if (ky >= 0 && ky <= 2) {
                        #pragma unroll
                        for (int kx = 0; kx < 3; kx++) {
                            u64 wv = w[ky * 3 + kx];
                            #pragma unroll
                            for (int ox = 0; ox < 14; ox++)
                                acc[pr][ox] = fma2(arow[ox + kx], wv, acc[pr][ox]);
                        }
                    }
                }
            }
        }
        int s = s0 + sp;
        float* z0 = g_Z + s * 980 + (2 * ocp) * 49 + py * 7;
        #pragma unroll
        for (int px = 0; px < 7; px++) {
            float a, b, c, d, e, f, g, h;
            unpack2(acc[0][2 * px],     a, b);
            unpack2(acc[0][2 * px + 1], c, d);
            unpack2(acc[1][2 * px],     e, f);
            unpack2(acc[1][2 * px + 1], g, h);
            z0[px]      = (a >= 1.f || c >= 1.f || e >= 1.f || g >= 1.f) ? 1.f : 0.f;
            z0[49 + px] = (b >= 1.f || d >= 1.f || f >= 1.f || h >= 1.f) ? 1.f : 0.f;
        }
    }
}

// ===========================================================================
// K2: split-K GEMM. grid (128, 4), block 256. BM=32, seg=245 k (7 chunks of 35).
// Thread (tx 0..15, ty 0..15): m-pair (2ty, 2ty+1), n = tx+16j (j<7).
// smem: Zs[35][34] floats (k-major, padded), Ws2[35][112] u64 (w duplicated).
// ===========================================================================
#define K2_SMEM (35*34*4 + 35*112*8)   // 4760 + 31360 = 36120

__global__ void __launch_bounds__(256)
k2_gemm()
{
    extern __shared__ char smraw[];
    float* Zs  = (float*)smraw;             // [35][34]
    u64*   Ws2 = (u64*)(smraw + 4760);      // [35][112]

    const int tid = threadIdx.x;
    const int tx  = tid & 15, ty = tid >> 4;
    const int m0  = blockIdx.x * 32;
    const int seg = blockIdx.y;
    const int k0  = seg * 245;

    u64 acc[7];
    #pragma unroll
    for (int j = 0; j < 7; j++) acc[j] = 0ull;

    for (int c0 = 0; c0 < 245; c0 += 35) {
        __syncthreads();
        for (int e = tid; e < 1120; e += 256) {
            int m = e / 35, k = e - m * 35;
            Zs[k * 34 + m] = g_Z[(m0 + m) * 980 + k0 + c0 + k];
        }
        for (int e = tid; e < 3920; e += 256) {
            int k = e / 112, n = e - k * 112;
            float w = g_Wt[(k0 + c0 + k) * 112 + n];
            Ws2[e] = pack2(w, w);
        }
        __syncthreads();
        #pragma unroll 5
        for (int k = 0; k < 35; k++) {
            u64 z = *(const u64*)(Zs + k * 34 + 2 * ty);
            const u64* wr = Ws2 + k * 112 + tx;
            #pragma unroll
            for (int j = 0; j < 7; j++)
                acc[j] = fma2(z, wr[16 * j], acc[j]);
        }
    }

    float* p = g_P + seg * (NB * 112) + (m0 + 2 * ty) * 112;
    #pragma unroll
    for (int j = 0; j < 7; j++) {
        float a, b; unpack2(acc[j], a, b);
        p[tx + 16 * j]       = a;
        p[112 + tx + 16 * j] = b;
    }
}

// ===========================================================================
// K3: one warp per sample. grid 512, block 256 (8 warps = 8 samples).
// ===========================================================================
__device__ __forceinline__ uint32 lifmask(float h){
    float v = 0.f; uint32 m = 0u;
    #pragma unroll
    for (int t = 0; t < 32; t++) {
        v += (h - v) * 0.5f;
        if (v >= 1.f) { m |= (1u << t); v = 0.f; }
    }
    return m;
}

__global__ void __launch_bounds__(256)
k3_lif(const float* __restrict__ Wf2, float* __restrict__ out)
{
    __shared__ u64    W2p[500];          // i-pairs: W2p[p][j] = (Wf2[2p][j], Wf2[2p+1][j])
    __shared__ uint32 Msk[8 * 100];
    __shared__ float  ysm[8 * 320];
    __shared__ float  cs[8 * 16];

    const int tid  = threadIdx.x;
    const int wid  = tid >> 5, lane = tid & 31;
    const int m    = blockIdx.x * 8 + wid;

    for (int e = tid; e < 500; e += 256) {
        int p = e / 100, j = e - p * 100;
        W2p[e] = pack2(Wf2[(2 * p) * 100 + j], Wf2[(2 * p + 1) * 100 + j]);
    }
    __syncthreads();

    // Phase A+B: sum split-K partials, LIF-1 masks
    #pragma unroll
    for (int q = 0; q < 4; q++) {
        int n = q * 32 + lane;
        if (n < 100) {
            int idx = m * 112 + n;
            float h = g_P[idx] + g_P[NB * 112 + idx]
                    + g_P[2 * NB * 112 + idx] + g_P[3 * NB * 112 + idx];
            Msk[wid * 100 + n] = lifmask(h);
        }
    }
    __syncwarp();

    // Phase C: lane = timestep t; y[i] via i-paired fma2
    {
        u64 y[5];
        #pragma unroll
        for (int p = 0; p < 5; p++) y[p] = 0ull;
        const uint32* mk = Msk + wid * 100;
        #pragma unroll 4
        for (int j = 0; j < 100; j++) {
            u64 b = splat2((float)((mk[j] >> lane) & 1u));
            #pragma unroll
            for (int p = 0; p < 5; p++)
                y[p] = fma2(b, W2p[p * 100 + j], y[p]);
        }
        float* yr = ysm + wid * 320 + lane * 10;
        #pragma unroll
        for (int p = 0; p < 5; p++) {
            float a, bb; unpack2(y[p], a, bb);
            yr[2 * p] = a; yr[2 * p + 1] = bb;
        }
    }
    __syncwarp();

    // Phase D: v2 LIF + softmax
    if (lane < 10) {
        float v = 0.f, cnt = 0.f;
        const float* yr = ysm + wid * 320;
        #pragma unroll
        for (int t = 0; t < 32; t++) {
            float yv = yr[t * 10 + lane];
            v += (yv - v) * 0.5f;
            if (v >= 1.f) { cnt += 1.f; v = 0.f; }
        }
        cs[wid * 16 + lane] = cnt * (1.f / 32.f);
    }
    __syncwarp();
    if (lane < 10) {
        const float* c = cs + wid * 16;
        float mx = -1e30f;
        #pragma unroll
        for (int q = 0; q < 10; q++) mx = fmaxf(mx, c[q]);
        float sum = 0.f;
        #pragma unroll
        for (int q = 0; q < 10; q++) sum += expf(c[q] - mx);
        out[m * 10 + lane] = expf(c[lane] - mx) / sum;
    }
}

// ===========================================================================
extern "C" void kernel_launch(void* const* d_in, const int* in_sizes, int n_in,
                              void* d_out, int out_size)
{
    const float* x   = (const float*)d_in[0];
    const float* Wc1 = (const float*)d_in[1];
    const float* Wc2 = (const float*)d_in[2];
    const float* Wf1 = (const float*)d_in[3];
    const float* Wf2 = (const float*)d_in[4];
    float* out = (float*)d_out;

    cudaFuncSetAttribute(k1_conv, cudaFuncAttributeMaxDynamicSharedMemorySize, K1_SMEM);
    cudaFuncSetAttribute(k2_gemm, cudaFuncAttributeMaxDynamicSharedMemorySize, K2_SMEM);

    kT<<<(980 * 112 + 255) / 256, 256>>>(Wf1);
    k1_conv<<<NB / 2, 160, K1_SMEM>>>(x, Wc1, Wc2);
    dim3 g2(128, 4);
    k2_gemm<<<g2, 256, K2_SMEM>>>();
    k3_lif<<<NB / 8, 256>>>(Wf2, out);
}

// round 8
// speedup vs baseline: 1.8067x; 1.1999x over previous
#include <cuda_runtime.h>
#include <math.h>

// Spiking CNN forward, B=4096.

#define NB 4096
typedef unsigned long long u64;
typedef unsigned int uint32;

__device__ float g_Z[NB * 980];          // binary conv-stack output [m][k]
__device__ u64   g_Wp[980 * 64];         // Wf1 n-pairs: g_Wp[k][np] = (Wf1[2np][k], Wf1[2np+1][k]), pad 0
__device__ float g_P[7 * NB * 128];      // split-K partial H (n padded to 128)

// ---- packed f32x2 helpers ----
__device__ __forceinline__ u64 splat2(float a){
    u64 r; asm("mov.b64 %0, {%1, %1};" : "=l"(r) : "f"(a)); return r;
}
__device__ __forceinline__ u64 pack2(float a, float b){
    u64 r; asm("mov.b64 %0, {%1, %2};" : "=l"(r) : "f"(a), "f"(b)); return r;
}
__device__ __forceinline__ void unpack2(u64 v, float &x, float &y){
    asm("mov.b64 {%0, %1}, %2;" : "=f"(x), "=f"(y) : "l"(v));
}
__device__ __forceinline__ u64 fma2(u64 a, u64 b, u64 c){
    u64 d; asm("fma.rn.f32x2 %0, %1, %2, %3;" : "=l"(d) : "l"(a), "l"(b), "l"(c));
    return d;
}

// ===========================================================================
// kT: g_Wp[k][np] = (Wf1[2np][k], Wf1[2np+1][k])
// ===========================================================================
__global__ void __launch_bounds__(256)
kT(const float* __restrict__ Wf1)
{
    int idx = blockIdx.x * 256 + threadIdx.x;
    if (idx < 980 * 64) {
        int k = idx >> 6, np = idx & 63;
        int n0 = 2 * np;
        float w0 = (n0     < 100) ? Wf1[n0 * 980 + k]       : 0.f;
        float w1 = (n0 + 1 < 100) ? Wf1[(n0 + 1) * 980 + k] : 0.f;
        g_Wp[idx] = pack2(w0, w1);
    }
}

// ===========================================================================
// K1: fused conv stack (unchanged from R7; g_Z row-major)
// ===========================================================================
#define K1_SMEM 58280

__global__ void __launch_bounds__(160)
k1_conv(const float* __restrict__ x, const float* __restrict__ Wc1,
        const float* __restrict__ Wc2)
{
    extern __shared__ char smraw[];
    float* xs  = (float*)(smraw);            // [2][30][30]
    u64*   w1p = (u64*)  (smraw + 7200);     // [5 ocp][9]
    u64*   w2p = (u64*)  (smraw + 7560);     // [10 ocp][90]
    float* p1s = (float*)(smraw + 14760);    // [2][10][16][34]

    const int tid = threadIdx.x;
    const int s0  = blockIdx.x * 2;

    for (int i = tid; i < 1800; i += 160) {
        int sp = i / 900, e = i - sp * 900;
        int r = e / 30, c = e - r * 30;
        float v = 0.f;
        if (r >= 1 && r <= 28 && c >= 1 && c <= 28)
            v = x[(s0 + sp) * 784 + (r - 1) * 28 + (c - 1)];
        xs[i] = v;
    }
    if (tid < 45) {
        int cp = tid / 9, k = tid - cp * 9;
        w1p[tid] = pack2(Wc1[(2 * cp) * 9 + k], Wc1[(2 * cp + 1) * 9 + k]);
    }
    for (int i = tid; i < 900; i += 160) {
        int ocp = i / 90, t = i - ocp * 90;
        w2p[i] = pack2(Wc2[(2 * ocp) * 90 + t], Wc2[(2 * ocp + 1) * 90 + t]);
    }
    for (int i = tid; i < 10880; i += 160) p1s[i] = 0.f;
    __syncthreads();

    for (int task = tid; task < 1960; task += 160) {
        int sp  = task / 980;
        int r   = task - sp * 980;
        int cp  = r / 196;
        int pos = r - cp * 196;
        int py = pos / 14, px = pos - py * 14;
        const float* xb = xs + sp * 900 + (2 * py) * 30 + 2 * px;
        u64 acc[2][2];
        acc[0][0] = acc[0][1] = acc[1][0] = acc[1][1] = 0ull;
        #pragma unroll
        for (int rr = 0; rr < 4; rr++) {
            u64 cc[4];
            #pragma unroll
            for (int c = 0; c < 4; c++) cc[c] = splat2(xb[rr * 30 + c]);
            #pragma unroll
            for (int dy = 0; dy < 2; dy++) {
                int ky = rr - dy;
                if (ky >= 0 && ky <= 2) {
                    #pragma unroll
                    for (int kx = 0; kx < 3; kx++) {
                        u64 w = w1p[cp * 9 + ky * 3 + kx];
                        acc[dy][0] = fma2(cc[kx],     w, acc[dy][0]);
                        acc[dy][1] = fma2(cc[kx + 1], w, acc[dy][1]);
                    }
                }
            }
        }
        float f0 = 0.f, f1 = 0.f, lo, hi;
        #pragma unroll
        for (int dy = 0; dy < 2; dy++)
            #pragma unroll
            for (int dx = 0; dx < 2; dx++) {
                unpack2(acc[dy][dx], lo, hi);
                if (lo >= 1.f) f0 = 1.f;
                if (hi >= 1.f) f1 = 1.f;
            }
        int base = ((sp * 10 + 2 * cp) * 16 + (py + 1)) * 34 + 2 * (px + 1);
        p1s[base]       = f0; p1s[base + 1]   = f0;
        p1s[base + 544] = f1; p1s[base + 545] = f1;
    }
    __syncthreads();

    if (tid < 140) {
        int sp  = tid / 70;
        int r70 = tid - sp * 70;
        int ocp = r70 / 7, py = r70 - ocp * 7;
        u64 acc[2][14];
        #pragma unroll
        for (int i = 0; i < 2; i++)
            #pragma unroll
            for (int j = 0; j < 14; j++) acc[i][j] = 0ull;

        const float* pbase = p1s + sp * 5440 + (2 * py) * 34;
        const u64*   wq    = w2p + ocp * 90;

        for (int ic = 0; ic < 10; ic++) {
            u64 w[9];
            #pragma unroll
            for (int k = 0; k < 9; k++) w[k] = wq[ic * 9 + k];
            const float* prow = pbase + ic * 544;
            #pragma unroll
            for (int rr = 0; rr < 4; rr++) {
                u64 arow[16];
                #pragma unroll
                for (int c = 0; c < 16; c++)
                    arow[c] = *(const u64*)(prow + rr * 34 + 2 * c);
                #pragma unroll
                for (int pr = 0; pr < 2; pr++) {
                    int ky = rr - pr;
                    if (ky >= 0 && ky <= 2) {
                        #pragma unroll
                        for (int kx = 0; kx < 3; kx++) {
                            u64 wv = w[ky * 3 + kx];
                            #pragma unroll
                            for (int ox = 0; ox < 14; ox++)
                                acc[pr][ox] = fma2(arow[ox + kx], wv, acc[pr][ox]);
                        }
                    }
                }
            }
        }
        int s = s0 + sp;
        float* z0 = g_Z + s * 980 + (2 * ocp) * 49 + py * 7;
        #pragma unroll
        for (int px = 0; px < 7; px++) {
            float a, b, c, d, e, f, g, h;
            unpack2(acc[0][2 * px],     a, b);
            unpack2(acc[0][2 * px + 1], c, d);
            unpack2(acc[1][2 * px],     e, f);
            unpack2(acc[1][2 * px + 1], g, h);
            z0[px]      = (a >= 1.f || c >= 1.f || e >= 1.f || g >= 1.f) ? 1.f : 0.f;
            z0[49 + px] = (b >= 1.f || d >= 1.f || f >= 1.f || h >= 1.f) ? 1.f : 0.f;
        }
    }
}

// ===========================================================================
// K2: split-K GEMM, n-pair packing. grid (64, 7), block 256.
// BM=64, seg=140 k (4 chunks of 35). Thread (tx,ty): m = ty+16i (i<4),
// n-pair = tx+16j (j<4). Per k: 4 LDS32 z + 4 splat + 4 LDS64 w + 16 fma2.
// ===========================================================================
#define K2_SMEM (9104 + 35*64*8)    // Zs[35][65] f (9100->9104) + Ws[35][64] u64

__global__ void __launch_bounds__(256)
k2_gemm()
{
    extern __shared__ char smraw[];
    float* Zs = (float*)smraw;              // [35][65]
    u64*   Ws = (u64*)(smraw + 9104);       // [35][64]

    const int tid = threadIdx.x;
    const int tx  = tid & 15, ty = tid >> 4;
    const int m0  = blockIdx.x * 64;
    const int k0  = blockIdx.y * 140;

    u64 acc[4][4];
    #pragma unroll
    for (int i = 0; i < 4; i++)
        #pragma unroll
        for (int j = 0; j < 4; j++) acc[i][j] = 0ull;

    for (int c0 = 0; c0 < 140; c0 += 35) {
        __syncthreads();
        for (int e = tid; e < 2240; e += 256) {
            int m = e / 35, k = e - m * 35;
            Zs[k * 65 + m] = g_Z[(m0 + m) * 980 + k0 + c0 + k];
        }
        for (int e = tid; e < 2240; e += 256) {
            int k = e >> 6, np = e & 63;
            Ws[e] = g_Wp[(k0 + c0 + k) * 64 + np];
        }
        __syncthreads();
        #pragma unroll 5
        for (int k = 0; k < 35; k++) {
            u64 zz[4];
            #pragma unroll
            for (int i = 0; i < 4; i++) zz[i] = splat2(Zs[k * 65 + ty + 16 * i]);
            #pragma unroll
            for (int j = 0; j < 4; j++) {
                u64 w = Ws[k * 64 + tx + 16 * j];
                #pragma unroll
                for (int i = 0; i < 4; i++)
                    acc[i][j] = fma2(zz[i], w, acc[i][j]);
            }
        }
    }

    u64* p = (u64*)g_P + blockIdx.y * (NB * 64);
    #pragma unroll
    for (int i = 0; i < 4; i++) {
        int m = m0 + ty + 16 * i;
        #pragma unroll
        for (int j = 0; j < 4; j++)
            p[m * 64 + tx + 16 * j] = acc[i][j];
    }
}

// ===========================================================================
// K3: one warp per sample. grid 512, block 256 (8 warps = 8 samples).
// ===========================================================================
__device__ __forceinline__ uint32 lifmask(float h){
    float v = 0.f; uint32 m = 0u;
    #pragma unroll
    for (int t = 0; t < 32; t++) {
        v += (h - v) * 0.5f;
        if (v >= 1.f) { m |= (1u << t); v = 0.f; }
    }
    return m;
}

__global__ void __launch_bounds__(256)
k3_lif(const float* __restrict__ Wf2, float* __restrict__ out)
{
    __shared__ u64    W2p[500];          // i-pairs: W2p[p][j] = (Wf2[2p][j], Wf2[2p+1][j])
    __shared__ uint32 Msk[8 * 100];
    __shared__ float  ysm[8 * 320];
    __shared__ float  cs[8 * 16];

    const int tid  = threadIdx.x;
    const int wid  = tid >> 5, lane = tid & 31;
    const int m    = blockIdx.x * 8 + wid;

    for (int e = tid; e < 500; e += 256) {
        int p = e / 100, j = e - p * 100;
        W2p[e] = pack2(Wf2[(2 * p) * 100 + j], Wf2[(2 * p + 1) * 100 + j]);
    }
    __syncthreads();

    // Phase A+B: sum 7 split-K partials, LIF-1 masks
    #pragma unroll
    for (int q = 0; q < 4; q++) {
        int n = q * 32 + lane;
        if (n < 100) {
            int idx = m * 128 + n;
            float h = 0.f;
            #pragma unroll
            for (int s = 0; s < 7; s++) h += g_P[s * (NB * 128) + idx];
            Msk[wid * 100 + n] = lifmask(h);
        }
    }
    __syncwarp();

    // Phase C: lane = timestep t; y[i] via i-paired fma2
    {
        u64 y[5];
        #pragma unroll
        for (int p = 0; p < 5; p++) y[p] = 0ull;
        const uint32* mk = Msk + wid * 100;
        #pragma unroll 4
        for (int j = 0; j < 100; j++) {
            u64 b = splat2((float)((mk[j] >> lane) & 1u));
            #pragma unroll
            for (int p = 0; p < 5; p++)
                y[p] = fma2(b, W2p[p * 100 + j], y[p]);
        }
        float* yr = ysm + wid * 320 + lane * 10;
        #pragma unroll
        for (int p = 0; p < 5; p++) {
            float a, bb; unpack2(y[p], a, bb);
            yr[2 * p] = a; yr[2 * p + 1] = bb;
        }
    }
    __syncwarp();

    // Phase D: v2 LIF + softmax
    if (lane < 10) {
        float v = 0.f, cnt = 0.f;
        const float* yr = ysm + wid * 320;
        #pragma unroll
        for (int t = 0; t < 32; t++) {
            float yv = yr[t * 10 + lane];
            v += (yv - v) * 0.5f;
            if (v >= 1.f) { cnt += 1.f; v = 0.f; }
        }
        cs[wid * 16 + lane] = cnt * (1.f / 32.f);
    }
    __syncwarp();
    if (lane < 10) {
        const float* c = cs + wid * 16;
        float mx = -1e30f;
        #pragma unroll
        for (int q = 0; q < 10; q++) mx = fmaxf(mx, c[q]);
        float sum = 0.f;
        #pragma unroll
        for (int q = 0; q < 10; q++) sum += expf(c[q] - mx);
        out[m * 10 + lane] = expf(c[lane] - mx) / sum;
    }
}

// ===========================================================================
extern "C" void kernel_launch(void* const* d_in, const int* in_sizes, int n_in,
                              void* d_out, int out_size)
{
    const float* x   = (const float*)d_in[0];
    const float* Wc1 = (const float*)d_in[1];
    const float* Wc2 = (const float*)d_in[2];
    const float* Wf1 = (const float*)d_in[3];
    const float* Wf2 = (const float*)d_in[4];
    float* out = (float*)d_out;

    cudaFuncSetAttribute(k1_conv, cudaFuncAttributeMaxDynamicSharedMemorySize, K1_SMEM);
    cudaFuncSetAttribute(k2_gemm, cudaFuncAttributeMaxDynamicSharedMemorySize, K2_SMEM);

    kT<<<(980 * 64 + 255) / 256, 256>>>(Wf1);
    k1_conv<<<NB / 2, 160, K1_SMEM>>>(x, Wc1, Wc2);
    dim3 g2(64, 7);
    k2_gemm<<<g2, 256, K2_SMEM>>>();
    k3_lif<<<NB / 8, 256>>>(Wf2, out);
}